// round 17
// baseline (speedup 1.0000x reference)
#include <cuda_runtime.h>
#include <cstdint>
#include <cstddef>

#define Bz 32
#define Dd 1024
#define Ff 512
#define Hh 16
#define Oo 4
#define FC 4096
#define CH 16           // wsum chunks
#define FL 32           // frames per chunk
#define NK 8            // gemm k-splits (k-chunk 512)

// Deterministic scratch (no device allocation allowed)
__device__ float g_logits[Oo * Bz * Hh * Ff];        // [o][b][h][f]  4 MB
__device__ float g_hcat_part[CH * Bz * FC];          // [chunk][b][o*1024+d] 8 MB
__device__ float g_hcat[Bz * FC];                    // [b][o*1024+d]  512 KB
__device__ float g_hidden_part[NK * Bz * FC];        // [kblk][b][j]  4 MB
__device__ float g_out_part[Bz * 8 * 4];             // [b][jc][n]
__device__ float g_dummy;

__global__ void k_dummy() { g_dummy = 1.0f; }

// ---------------------------------------------------------------------------
// Kernel A: logits[o,b,h,f] = (x[f,b,h,:] . q[o,h,:]) / 8, masked to -50
// No smem; q in registers, x streamed via full-sector LDG.128.
// ---------------------------------------------------------------------------
__global__ void __launch_bounds__(256) k_logits(const float* __restrict__ x,
                                                const int* __restrict__ nfp,
                                                const float* __restrict__ q) {
    int b  = blockIdx.x;
    int fg = blockIdx.y;             // 8 groups of 64 frames
    int hg = blockIdx.z;             // 2 h-groups
    int t = threadIdx.x;             // 256
    int w = t >> 5, lane = t & 31;
    int h = hg * 8 + w;
    int fl = lane >> 2, sg = lane & 3;
    int nf = nfp[b];

    float4 qr[4][4];
    const float4* qbase = (const float4*)(q + h * 64 + sg * 16);
#pragma unroll
    for (int o = 0; o < 4; o++)
#pragma unroll
        for (int i = 0; i < 4; i++)
            qr[o][i] = qbase[o * 256 + i];

    for (int ft = 0; ft < 8; ft++) {
        int fbase = fg * 64 + ft * 8;
        int f = fbase + fl;
        float a0 = 0.f, a1 = 0.f, a2 = 0.f, a3 = 0.f;
        if (fbase < nf) {            // block-uniform guard
            const float4* xp = (const float4*)
                (x + ((size_t)f * Bz + b) * Dd + h * 64 + sg * 16);
            float4 xr[4];
#pragma unroll
            for (int i = 0; i < 4; i++) xr[i] = xp[i];
#pragma unroll
            for (int i = 0; i < 4; i++) {
                a0 = fmaf(xr[i].x, qr[0][i].x, a0);
                a0 = fmaf(xr[i].y, qr[0][i].y, a0);
                a0 = fmaf(xr[i].z, qr[0][i].z, a0);
                a0 = fmaf(xr[i].w, qr[0][i].w, a0);
                a1 = fmaf(xr[i].x, qr[1][i].x, a1);
                a1 = fmaf(xr[i].y, qr[1][i].y, a1);
                a1 = fmaf(xr[i].z, qr[1][i].z, a1);
                a1 = fmaf(xr[i].w, qr[1][i].w, a1);
                a2 = fmaf(xr[i].x, qr[2][i].x, a2);
                a2 = fmaf(xr[i].y, qr[2][i].y, a2);
                a2 = fmaf(xr[i].z, qr[2][i].z, a2);
                a2 = fmaf(xr[i].w, qr[2][i].w, a2);
                a3 = fmaf(xr[i].x, qr[3][i].x, a3);
                a3 = fmaf(xr[i].y, qr[3][i].y, a3);
                a3 = fmaf(xr[i].z, qr[3][i].z, a3);
                a3 = fmaf(xr[i].w, qr[3][i].w, a3);
            }
        }
        a0 += __shfl_xor_sync(0xffffffffu, a0, 1);
        a0 += __shfl_xor_sync(0xffffffffu, a0, 2);
        a1 += __shfl_xor_sync(0xffffffffu, a1, 1);
        a1 += __shfl_xor_sync(0xffffffffu, a1, 2);
        a2 += __shfl_xor_sync(0xffffffffu, a2, 1);
        a2 += __shfl_xor_sync(0xffffffffu, a2, 2);
        a3 += __shfl_xor_sync(0xffffffffu, a3, 1);
        a3 += __shfl_xor_sync(0xffffffffu, a3, 2);
        if (sg == 0) {
            bool valid = f < nf;
            size_t base = ((size_t)b * Hh + h) * Ff + f;
            g_logits[base]                      = valid ? a0 * 0.125f : -50.0f;
            g_logits[base + (size_t)Bz*Hh*Ff]   = valid ? a1 * 0.125f : -50.0f;
            g_logits[base + (size_t)2*Bz*Hh*Ff] = valid ? a2 * 0.125f : -50.0f;
            g_logits[base + (size_t)3*Bz*Hh*Ff] = valid ? a3 * 0.125f : -50.0f;
        }
    }
}

// ---------------------------------------------------------------------------
// Kernel B: softmax. 256 blocks, warp-per-h, register rows, smem transpose.
// ---------------------------------------------------------------------------
__global__ void k_softmax(float* __restrict__ attn) {
    int bid = blockIdx.x;            // 256
    int o = bid >> 6;
    int b = (bid >> 1) & 31;
    int hg = bid & 1;
    int t = threadIdx.x;             // 256
    int w = t >> 5, lane = t & 31;
    int h = hg * 8 + w;

    __shared__ float ps[8 * 524];

    const float* src = g_logits + ((size_t)(o * Bz + b) * Hh + h) * Ff;
    float v[16];
    float m = -1e30f;
#pragma unroll
    for (int i = 0; i < 16; i++) {
        v[i] = src[lane + i * 32];
        m = fmaxf(m, v[i]);
    }
#pragma unroll
    for (int off = 16; off; off >>= 1)
        m = fmaxf(m, __shfl_xor_sync(0xffffffffu, m, off));
    float s = 0.f;
#pragma unroll
    for (int i = 0; i < 16; i++) {
        v[i] = __expf(v[i] - m);
        s += v[i];
    }
#pragma unroll
    for (int off = 16; off; off >>= 1)
        s += __shfl_xor_sync(0xffffffffu, s, off);
    float inv = 1.0f / s;
#pragma unroll
    for (int i = 0; i < 16; i++)
        ps[w * 524 + lane + i * 32] = v[i] * inv;
    __syncthreads();

    float* dst = attn + (size_t)o * (Ff * Bz * Hh) + b * Hh + hg * 8;
    for (int i = t; i < 4096; i += 256) {
        int f = i >> 3, hl = i & 7;
        dst[(size_t)f * (Bz * Hh) + hl] = ps[hl * 524 + f];
    }
}

// ---------------------------------------------------------------------------
// Kernel C: partial weighted sums, 16 chunks x 32 frames (unroll 16).
// ---------------------------------------------------------------------------
__global__ void k_wsum(const float* __restrict__ x, const int* __restrict__ nfp,
                       const float* __restrict__ attn) {
    int b = blockIdx.x;
    int c = blockIdx.y;
    int f0 = c * FL;
    int nf = nfp[b];
    int d = threadIdx.x;
    int h = d >> 6;

    __shared__ float as[Oo * FL * Hh];   // [o][fl][h] 8 KB
    float a0 = 0.f, a1 = 0.f, a2 = 0.f, a3 = 0.f;

    if (f0 < nf) {
        for (int i = d; i < Oo * FL * Hh; i += 1024) {
            int o = i >> 9, r = i & 511;
            as[i] = attn[(size_t)o * (Ff * Bz * Hh) +
                         (size_t)(f0 + (r >> 4)) * (Bz * Hh) + b * Hh + (r & 15)];
        }
        __syncthreads();
        int fe = min(FL, nf - f0);
        const float* xp = x + ((size_t)f0 * Bz + b) * Dd + d;
        if (fe == FL) {
#pragma unroll 16
            for (int fl = 0; fl < FL; fl++) {
                float xv = xp[(size_t)fl * (Bz * Dd)];
                int ai = fl * 16 + h;
                a0 = fmaf(xv, as[ai],       a0);
                a1 = fmaf(xv, as[512 + ai], a1);
                a2 = fmaf(xv, as[1024 + ai], a2);
                a3 = fmaf(xv, as[1536 + ai], a3);
            }
        } else {
            for (int fl = 0; fl < fe; fl++) {
                float xv = xp[(size_t)fl * (Bz * Dd)];
                int ai = fl * 16 + h;
                a0 = fmaf(xv, as[ai],       a0);
                a1 = fmaf(xv, as[512 + ai], a1);
                a2 = fmaf(xv, as[1024 + ai], a2);
                a3 = fmaf(xv, as[1536 + ai], a3);
            }
        }
    }
    float* p = g_hcat_part + ((size_t)c * Bz + b) * FC + d;
    p[0] = a0; p[1024] = a1; p[2048] = a2; p[3072] = a3;
}

// Reduce 16 chunk partials into hcat. (Impl-insensitive ~6us: ramp-dominated.)
__global__ void k_csum() {
    int i = blockIdx.x * 256 + threadIdx.x;
    float s = 0.f;
#pragma unroll
    for (int c = 0; c < CH; c++) s += g_hcat_part[(size_t)c * (Bz * FC) + i];
    g_hcat[i] = s;
}

// ---------------------------------------------------------------------------
// Kernel D: 3xTF32 tensor-core GEMM. NK=8 (k-chunk 512) -> 256 blocks =
// single wave @2/SM. A staged once as f32 (66KB), hi/lo split at fragment
// load. 4 W buffers, prefetch distance 3, wait_group 2.
// ---------------------------------------------------------------------------
#define AP 516          // A smem row pitch: 516 mod 32 = 4 -> (4g+tg) conflict-free
#define WP 136
#define WSTG (16 * WP)

__device__ __forceinline__ uint32_t f2tf32(float x) {
    uint32_t r;
    asm("cvt.rna.tf32.f32 %0, %1;" : "=r"(r) : "f"(x));
    return r;
}

__device__ __forceinline__ void split_tf32(float v, uint32_t& hi, uint32_t& lo) {
    hi = f2tf32(v);
    lo = f2tf32(v - __uint_as_float(hi));
}

__device__ __forceinline__ void mma_tf32(float* d, const uint32_t* a,
                                         uint32_t b0, uint32_t b1) {
    asm("mma.sync.aligned.m16n8k8.row.col.f32.tf32.tf32.f32 "
        "{%0,%1,%2,%3}, {%4,%5,%6,%7}, {%8,%9}, {%0,%1,%2,%3};"
        : "+f"(d[0]), "+f"(d[1]), "+f"(d[2]), "+f"(d[3])
        : "r"(a[0]), "r"(a[1]), "r"(a[2]), "r"(a[3]), "r"(b0), "r"(b1));
}

__device__ __forceinline__ void cp16(float* dst, const float* src) {
    uint32_t d = (uint32_t)__cvta_generic_to_shared(dst);
    asm volatile("cp.async.cg.shared.global [%0], [%1], 16;"
                 :: "r"(d), "l"(src) : "memory");
}

__global__ void __launch_bounds__(256, 2) k_gemm1(const float* __restrict__ W1) {
    extern __shared__ float smg[];
    float* As = smg;                 // 32 * AP (f32)
    float* Ws = As + 32 * AP;        // 4 * WSTG
    int t = threadIdx.x;
    int warp = t >> 5, lane = t & 31;
    int g = lane >> 2, tg = lane & 3;
    int jb = blockIdx.x * 128;
    int kb = blockIdx.y * 512;

    int wrow = t >> 5;
    int wcol = (t & 31) * 4;
    const float* wbase = W1 + (size_t)kb * FC + jb + wcol;

    // Prologue: W stages 0,1,2 in flight.
#pragma unroll
    for (int s = 0; s < 3; s++) {
        float* bb = Ws + s * WSTG;
        cp16(&bb[wrow * WP + wcol], wbase + (size_t)(s * 16 + wrow) * FC);
        cp16(&bb[(wrow + 8) * WP + wcol], wbase + (size_t)(s * 16 + wrow + 8) * FC);
        asm volatile("cp.async.commit_group;" ::: "memory");
    }

    // Stage A = hcat[0..31][kb..kb+511] as f32
    for (int idx = t; idx < 32 * 512; idx += 256) {
        int b = idx >> 9, c = idx & 511;
        As[b * AP + c] = g_hcat[b * FC + kb + c];
    }

    float d[2][2][4];
#pragma unroll
    for (int mt = 0; mt < 2; mt++)
#pragma unroll
        for (int nt = 0; nt < 2; nt++)
#pragma unroll
            for (int e = 0; e < 4; e++) d[mt][nt][e] = 0.f;

    for (int ks = 0; ks < 32; ks++) {
        asm volatile("cp.async.wait_group 2;" ::: "memory");
        __syncthreads();             // stage ks visible; buffer (ks+3)%4 free

        if (ks < 29) {
            float* bb = Ws + ((ks + 3) & 3) * WSTG;
            cp16(&bb[wrow * WP + wcol],
                 wbase + (size_t)((ks + 3) * 16 + wrow) * FC);
            cp16(&bb[(wrow + 8) * WP + wcol],
                 wbase + (size_t)((ks + 3) * 16 + wrow + 8) * FC);
        }
        asm volatile("cp.async.commit_group;" ::: "memory");

        const float* Wcur = Ws + (ks & 3) * WSTG;
#pragma unroll
        for (int sub = 0; sub < 2; sub++) {
            int ac = ks * 16 + sub * 8 + tg;
            uint32_t ah[2][4], al[2][4];
#pragma unroll
            for (int mt = 0; mt < 2; mt++) {
                int r0 = mt * 16 + g;
                split_tf32(As[r0 * AP + ac],           ah[mt][0], al[mt][0]);
                split_tf32(As[(r0 + 8) * AP + ac],     ah[mt][1], al[mt][1]);
                split_tf32(As[r0 * AP + ac + 4],       ah[mt][2], al[mt][2]);
                split_tf32(As[(r0 + 8) * AP + ac + 4], ah[mt][3], al[mt][3]);
            }
#pragma unroll
            for (int nt = 0; nt < 2; nt++) {
                int jc = warp * 16 + nt * 8 + g;
                float b0f = Wcur[(sub * 8 + tg) * WP + jc];
                float b1f = Wcur[(sub * 8 + tg + 4) * WP + jc];
                uint32_t bh0, bl0, bh1, bl1;
                split_tf32(b0f, bh0, bl0);
                split_tf32(b1f, bh1, bl1);
#pragma unroll
                for (int mt = 0; mt < 2; mt++) {
                    mma_tf32(d[mt][nt], ah[mt], bh0, bh1);
                    mma_tf32(d[mt][nt], al[mt], bh0, bh1);
                    mma_tf32(d[mt][nt], ah[mt], bl0, bl1);
                }
            }
        }
    }

    float* dst = g_hidden_part + (size_t)blockIdx.y * (Bz * FC);
#pragma unroll
    for (int mt = 0; mt < 2; mt++) {
#pragma unroll
        for (int nt = 0; nt < 2; nt++) {
            int j0 = jb + warp * 16 + nt * 8 + 2 * tg;
            int b0 = mt * 16 + g;
            *(float2*)&dst[(size_t)b0 * FC + j0] =
                make_float2(d[mt][nt][0], d[mt][nt][1]);
            *(float2*)&dst[(size_t)(b0 + 8) * FC + j0] =
                make_float2(d[mt][nt][2], d[mt][nt][3]);
        }
    }
}

// ---------------------------------------------------------------------------
// Kernel E1: fused slab-reduce + bias + ReLU + W2 partial dot.
// ---------------------------------------------------------------------------
__global__ void k_outp(const float* __restrict__ b1, const float* __restrict__ W2) {
    int bid = blockIdx.x;
    int b = bid >> 3, jc = bid & 7;
    int t = threadIdx.x;   // 256
    float a0 = 0.f, a1 = 0.f, a2 = 0.f, a3 = 0.f;

#pragma unroll
    for (int p = 0; p < 2; p++) {
        int j = jc * 512 + p * 256 + t;
        float s = b1[j];
#pragma unroll
        for (int kb = 0; kb < NK; kb++)
            s += g_hidden_part[(size_t)kb * (Bz * FC) + (size_t)b * FC + j];
        s = fmaxf(s, 0.f);
        float4 w = *(const float4*)(W2 + (size_t)j * 4);
        a0 = fmaf(s, w.x, a0);
        a1 = fmaf(s, w.y, a1);
        a2 = fmaf(s, w.z, a2);
        a3 = fmaf(s, w.w, a3);
    }
#pragma unroll
    for (int off = 16; off; off >>= 1) {
        a0 += __shfl_xor_sync(0xffffffffu, a0, off);
        a1 += __shfl_xor_sync(0xffffffffu, a1, off);
        a2 += __shfl_xor_sync(0xffffffffu, a2, off);
        a3 += __shfl_xor_sync(0xffffffffu, a3, off);
    }
    __shared__ float sred[8][4];
    if ((t & 31) == 0) {
        int w = t >> 5;
        sred[w][0] = a0; sred[w][1] = a1; sred[w][2] = a2; sred[w][3] = a3;
    }
    __syncthreads();
    if (t < 4) {
        float r = 0.f;
#pragma unroll
        for (int w = 0; w < 8; w++) r += sred[w][t];
        g_out_part[(b * 8 + jc) * 4 + t] = r;
    }
}

// Kernel E2: final reduce over 8 j-chunks.
__global__ void k_out2(const float* __restrict__ b2, float* __restrict__ out) {
    int i = threadIdx.x;      // 128 = 32 b x 4 n
    int b = i >> 2, n = i & 3;
    float r = b2[n];
#pragma unroll
    for (int jc = 0; jc < 8; jc++) r += g_out_part[(b * 8 + jc) * 4 + n];
    out[b * 4 + n] = r;
}

// ---------------------------------------------------------------------------
extern "C" void kernel_launch(void* const* d_in, const int* in_sizes, int n_in,
                              void* d_out, int out_size) {
    const float* x  = (const float*)d_in[0];
    const int*   nf = (const int*)  d_in[1];
    const float* q  = (const float*)d_in[2];
    const float* W1 = (const float*)d_in[3];
    const float* b1 = (const float*)d_in[4];
    const float* W2 = (const float*)d_in[5];
    const float* b2 = (const float*)d_in[6];

    float* out_p  = (float*)d_out;              // (B, 4) = 128 floats
    float* attn_p = out_p + Bz * Oo;            // (O, F, B, H) = 1,048,576 floats

    const int smemG = (32 * AP + 4 * WSTG) * 4;  // 100864 B
    cudaFuncSetAttribute(k_gemm1, cudaFuncAttributeMaxDynamicSharedMemorySize, smemG);

    k_dummy<<<1, 1>>>();                        // capture slot -> k_wsum

    dim3 gA(Bz, 8, 2);
    k_logits<<<gA, 256>>>(x, nf, q);

    k_softmax<<<256, 256>>>(attn_p);

    dim3 gC(Bz, CH);
    k_wsum<<<gC, 1024>>>(x, nf, attn_p);        // 4th launch (ncu)

    k_csum<<<(Bz * FC) / 256, 256>>>();

    dim3 gD(FC / 128, NK);
    k_gemm1<<<gD, 256, smemG>>>(W1);

    k_outp<<<Bz * 8, 256>>>(b1, W2);

    k_out2<<<1, 128>>>(b2, out_p);
}